// round 8
// baseline (speedup 1.0000x reference)
#include <cuda_runtime.h>
#include <cuda_bf16.h>
#include <math.h>
#include <stdint.h>

#define BB    8
#define CIN   64
#define HH    128
#define WW    128
#define COUT  128
#define NPIX  (HH*WW)           // 16384
#define KTOT  (9*CIN)           // 576

// Scratch (__device__ globals; no allocation)
__device__ float g_x2 [BB*NPIX*CIN];          // NHWC fp32: [b][h][w][c]
__device__ __nv_bfloat16 g_xbhi[BB*NPIX*CIN]; // NHWC bf16 hi
__device__ __nv_bfloat16 g_xblo[BB*NPIX*CIN]; // NHWC bf16 lo
__device__ float g_offm[BB*NPIX*32];          // per-pixel [32]: 0..17 off, 18..26 mask
__device__ uint4 g_wfhi[9*8*4*32];            // k3 A frags (hi): [kk][mtile8][ks4][lane32]
__device__ uint4 g_wflo[9*8*4*32];            // k3 A frags (lo)
__device__ uint4 g_w2fhi[9*2*4*32];           // k2 A frags (hi): [kk][mtile2][ks4][lane32]
__device__ uint4 g_w2flo[9*2*4*32];           // k2 A frags (lo)

__device__ __forceinline__ uint32_t pack_bf16x2(float e0, float e1) {
    uint32_t r;
    asm("cvt.rn.bf16x2.f32 %0, %1, %2;" : "=r"(r) : "f"(e1), "f"(e0));
    return r;
}
__device__ __forceinline__ float bf16_hi(float v) {
    __nv_bfloat16 hb = __float2bfloat16(v);
    return __bfloat162float(hb);
}
__device__ __forceinline__ void mma_bf16(float* d, const uint32_t* a, uint32_t b0, uint32_t b1) {
    asm volatile(
        "mma.sync.aligned.m16n8k16.row.col.f32.bf16.bf16.f32 "
        "{%0,%1,%2,%3}, {%4,%5,%6,%7}, {%8,%9}, {%0,%1,%2,%3};"
        : "+f"(d[0]), "+f"(d[1]), "+f"(d[2]), "+f"(d[3])
        : "r"(a[0]), "r"(a[1]), "r"(a[2]), "r"(a[3]), "r"(b0), "r"(b1));
}
__device__ __forceinline__ void bar_sync_n(int id) {
    asm volatile("bar.sync %0, %1;" :: "r"(id), "r"(320) : "memory");
}
__device__ __forceinline__ void bar_arrive_n(int id) {
    asm volatile("bar.arrive %0, %1;" :: "r"(id), "r"(320) : "memory");
}

// ---------------------------------------------------------------------------
// K0: weight prep — pre-packed mma A fragments (hi/lo) for k3 and k2.
// ---------------------------------------------------------------------------
__global__ void k0_wt(const float* __restrict__ rw,
                      const float* __restrict__ off_w,
                      const float* __restrict__ mod_w) {
    int i = blockIdx.x * 256 + threadIdx.x;
    if (i < 9 * 8 * 4 * 32) {
        int kk   = i >> 10;
        int rem  = i & 1023;
        int mt   = rem >> 7;
        int rem2 = rem & 127;
        int ks   = rem2 >> 5;
        int lane = rem2 & 31;
        int g = lane >> 2, t = lane & 3;
        int o0 = mt * 16 + g, o1 = o0 + 8;
        int c0 = ks * 16 + 2 * t, c1 = c0 + 8;

        float w00a = rw[(o0 * 64 + c0) * 9 + kk];
        float w00b = rw[(o0 * 64 + c0 + 1) * 9 + kk];
        float w10a = rw[(o1 * 64 + c0) * 9 + kk];
        float w10b = rw[(o1 * 64 + c0 + 1) * 9 + kk];
        float w01a = rw[(o0 * 64 + c1) * 9 + kk];
        float w01b = rw[(o0 * 64 + c1 + 1) * 9 + kk];
        float w11a = rw[(o1 * 64 + c1) * 9 + kk];
        float w11b = rw[(o1 * 64 + c1 + 1) * 9 + kk];

        float h00a = bf16_hi(w00a), h00b = bf16_hi(w00b);
        float h10a = bf16_hi(w10a), h10b = bf16_hi(w10b);
        float h01a = bf16_hi(w01a), h01b = bf16_hi(w01b);
        float h11a = bf16_hi(w11a), h11b = bf16_hi(w11b);

        uint4 hi, lo;
        hi.x = pack_bf16x2(h00a, h00b);
        hi.y = pack_bf16x2(h10a, h10b);
        hi.z = pack_bf16x2(h01a, h01b);
        hi.w = pack_bf16x2(h11a, h11b);
        lo.x = pack_bf16x2(w00a - h00a, w00b - h00b);
        lo.y = pack_bf16x2(w10a - h10a, w10b - h10b);
        lo.z = pack_bf16x2(w01a - h01a, w01b - h01b);
        lo.w = pack_bf16x2(w11a - h11a, w11b - h11b);
        g_wfhi[i] = hi;
        g_wflo[i] = lo;
    }
    if (i < 9 * 2 * 4 * 32) {
        int lane = i & 31;
        int ks = (i >> 5) & 3;
        int mt = (i >> 7) & 1;
        int kk = i >> 8;
        int g = lane >> 2, t = lane & 3;
        int o0 = mt * 16 + g, o1 = o0 + 8;
        int c0 = ks * 16 + 2 * t, c1 = c0 + 8;

        auto w2v = [&](int o, int c) -> float {
            if (o < 18)      return off_w[(o * 64 + c) * 9 + kk];
            else if (o < 27) return mod_w[((o - 18) * 64 + c) * 9 + kk];
            return 0.f;
        };
        float w00a = w2v(o0, c0), w00b = w2v(o0, c0 + 1);
        float w10a = w2v(o1, c0), w10b = w2v(o1, c0 + 1);
        float w01a = w2v(o0, c1), w01b = w2v(o0, c1 + 1);
        float w11a = w2v(o1, c1), w11b = w2v(o1, c1 + 1);

        float h00a = bf16_hi(w00a), h00b = bf16_hi(w00b);
        float h10a = bf16_hi(w10a), h10b = bf16_hi(w10b);
        float h01a = bf16_hi(w01a), h01b = bf16_hi(w01b);
        float h11a = bf16_hi(w11a), h11b = bf16_hi(w11b);

        uint4 hi, lo;
        hi.x = pack_bf16x2(h00a, h00b);
        hi.y = pack_bf16x2(h10a, h10b);
        hi.z = pack_bf16x2(h01a, h01b);
        hi.w = pack_bf16x2(h11a, h11b);
        lo.x = pack_bf16x2(w00a - h00a, w00b - h00b);
        lo.y = pack_bf16x2(w10a - h10a, w10b - h10b);
        lo.z = pack_bf16x2(w01a - h01a, w01b - h01b);
        lo.w = pack_bf16x2(w11a - h11a, w11b - h11b);
        g_w2fhi[i] = hi;
        g_w2flo[i] = lo;
    }
}

// ---------------------------------------------------------------------------
// K1: 1x1 pre-conv, NCHW in -> NHWC fp32 (g_x2) + NHWC bf16 hi/lo
// ---------------------------------------------------------------------------
__global__ void __launch_bounds__(128) k1_pre(const float* __restrict__ x,
                                              const float* __restrict__ pre_w,
                                              const float* __restrict__ pre_b) {
    __shared__ float wsm[64 * 64];
    __shared__ float bsm[64];
    int tid = threadIdx.x;
    for (int i = tid; i < 4096; i += 128) {
        int co = i & 63, ci = i >> 6;
        wsm[ci * 64 + co] = pre_w[co * 64 + ci];
    }
    if (tid < 64) bsm[tid] = pre_b[tid];
    __syncthreads();

    int bh = blockIdx.x;
    int b = bh >> 7, h = bh & 127;
    int w = tid;

    const float* xp = x + (size_t)b * 64 * NPIX + h * WW + w;
    float xin[64];
#pragma unroll
    for (int ci = 0; ci < 64; ci++) xin[ci] = xp[(size_t)ci * NPIX];

    size_t pbase = ((size_t)bh * WW + w) * 64;
    float4* out4 = (float4*)(g_x2 + pbase);
    const float4* wsm4 = (const float4*)wsm;
    const float4* b4 = (const float4*)bsm;
#pragma unroll
    for (int cog = 0; cog < 16; cog++) {
        float4 acc = b4[cog];
#pragma unroll
        for (int ci = 0; ci < 64; ci++) {
            float4 wv = wsm4[ci * 16 + cog];
            acc.x += xin[ci] * wv.x;
            acc.y += xin[ci] * wv.y;
            acc.z += xin[ci] * wv.z;
            acc.w += xin[ci] * wv.w;
        }
        out4[cog] = acc;
        float h0 = bf16_hi(acc.x), h1 = bf16_hi(acc.y);
        float h2 = bf16_hi(acc.z), h3 = bf16_hi(acc.w);
        uint2 vh = make_uint2(pack_bf16x2(h0, h1), pack_bf16x2(h2, h3));
        uint2 vl = make_uint2(pack_bf16x2(acc.x - h0, acc.y - h1),
                              pack_bf16x2(acc.z - h2, acc.w - h3));
        *(uint2*)(g_xbhi + pbase + cog * 4) = vh;
        *(uint2*)(g_xblo + pbase + cog * 4) = vl;
    }
}

// ---------------------------------------------------------------------------
// K2: offset+mask 3x3 conv via HMMA hi/lo 3-pass. (unchanged)
// ---------------------------------------------------------------------------
extern __shared__ float dyn_smem[];
#define S_STRIDE  144   // bytes per px row (72 bf16)

__global__ void __launch_bounds__(256) k2_offmask(const float* __restrict__ off_b,
                                                  const float* __restrict__ mod_b) {
    char* smp = (char*)dyn_smem;
    char* s_hi = smp;
    char* s_lo = smp + 18432;

    int tid = threadIdx.x;
    int warp = tid >> 5, lane = tid & 31;
    int g = lane >> 2, t = lane & 3;
    int bx = blockIdx.x;
    int b = bx >> 7, h = bx & 127;
    size_t pixbase = (size_t)bx * 128;

    int warp_m = warp >> 2;     // 0..1
    int warp_n = warp & 3;      // 0..3

    float acc[4][4];
#pragma unroll
    for (int nt = 0; nt < 4; nt++)
#pragma unroll
        for (int j = 0; j < 4; j++) acc[nt][j] = 0.f;

    for (int kk = 0; kk < 9; kk++) {
        int ky = kk / 3, kx = kk - ky * 3;
        __syncthreads();
        int y = h - 1 + ky;
        bool yok = (unsigned)y < 128u;
        const __nv_bfloat16* rh = g_xbhi + ((size_t)(b * 128 + (yok ? y : 0)) * 128) * 64;
        const __nv_bfloat16* rl = g_xblo + ((size_t)(b * 128 + (yok ? y : 0)) * 128) * 64;
        for (int i = tid; i < 2048; i += 256) {
            int px = i >> 4, c4 = i & 15;
            int xg = px - 1 + kx;
            uint2 vh = make_uint2(0u, 0u), vl = make_uint2(0u, 0u);
            if (yok && (unsigned)xg < 128u) {
                vh = *(const uint2*)(rh + xg * 64 + c4 * 4);
                vl = *(const uint2*)(rl + xg * 64 + c4 * 4);
            }
            *(uint2*)(s_hi + px * S_STRIDE + c4 * 8) = vh;
            *(uint2*)(s_lo + px * S_STRIDE + c4 * 8) = vl;
        }
        __syncthreads();

        const uint4* wfh = g_w2fhi + (kk * 2 + warp_m) * 4 * 32;
        const uint4* wfl = g_w2flo + (kk * 2 + warp_m) * 4 * 32;
#pragma unroll
        for (int ks = 0; ks < 4; ks++) {
            uint4 ah = __ldg(&wfh[ks * 32 + lane]);
            uint4 al = __ldg(&wfl[ks * 32 + lane]);
            uint32_t bh0[4], bh1[4], bl0[4], bl1[4];
#pragma unroll
            for (int nt = 0; nt < 4; nt++) {
                int npx = warp_n * 32 + nt * 8 + g;
                uint32_t base = (uint32_t)(npx * S_STRIDE + ks * 32 + t * 4);
                bh0[nt] = *(const uint32_t*)(s_hi + base);
                bh1[nt] = *(const uint32_t*)(s_hi + base + 16);
                bl0[nt] = *(const uint32_t*)(s_lo + base);
                bl1[nt] = *(const uint32_t*)(s_lo + base + 16);
            }
#pragma unroll
            for (int nt = 0; nt < 4; nt++) {
                mma_bf16(acc[nt], (const uint32_t*)&ah, bh0[nt], bh1[nt]);
                mma_bf16(acc[nt], (const uint32_t*)&ah, bl0[nt], bl1[nt]);
                mma_bf16(acc[nt], (const uint32_t*)&al, bh0[nt], bh1[nt]);
            }
        }
    }

    int o0 = warp_m * 16 + g, o1 = o0 + 8;
    auto wr = [&](int o, int px, float v) {
        if (o >= 27) return;
        v += (o < 18) ? __ldg(off_b + o) : __ldg(mod_b + o - 18);
        if (o >= 18) v = 2.0f / (1.0f + expf(-v));
        g_offm[(pixbase + px) * 32 + o] = v;
    };
#pragma unroll
    for (int nt = 0; nt < 4; nt++) {
        int px = warp_n * 32 + nt * 8 + 2 * t;
        wr(o0, px,     acc[nt][0]);
        wr(o0, px + 1, acc[nt][1]);
        wr(o1, px,     acc[nt][2]);
        wr(o1, px + 1, acc[nt][3]);
    }
}
#define K2_SMEM_BYTES 36864

// ---------------------------------------------------------------------------
// K3: warp-specialized deformable sampling + HMMA hi/lo 3-pass.
// Block = half row (64 px), 320 threads / 10 warps, 2 CTAs/SM.
//   warps 0-1: producers (gather + convert + STS, ping-pong buffers)
//   warps 2-9: consumers (pure HMMA, 32o x 32px tiles)
// Named barriers: 1,2 = full[p] (producers arrive, consumers sync)
//                 3,4 = free[p] (consumers arrive, producers sync)
// smem: s_hi[2],s_lo[2] (4x9216=36864) | OSM 36864 | IBUF 45312 | WBUF 54528
// ---------------------------------------------------------------------------
#define OSM_OFF   36864
#define IBUF_OFF  45312
#define WBUF_OFF  54528
#define K3_SMEM_BYTES 63744

__global__ void __launch_bounds__(320, 2) k3_main(float* __restrict__ out) {
    char* smp = (char*)dyn_smem;

    int tid = threadIdx.x;
    int warp = tid >> 5, lane = tid & 31;
    int g = lane >> 2, t = lane & 3;
    int bx = blockIdx.x;
    int b = bx >> 8;
    int h = (bx >> 1) & 127;
    int seg = bx & 1;
    int w0 = seg * 64;
    size_t pixbase = (((size_t)(b * 128 + h)) * 128 + w0);

    float* osm = (float*)(smp + OSM_OFF);
    int4* ibuf = (int4*)(smp + IBUF_OFF);
    float4* wbuf = (float4*)(smp + WBUF_OFF);

    for (int i = tid; i < 2048; i += 320) {
        int px = i >> 5, j = i & 31;
        osm[px * 33 + j] = g_offm[(pixbase + px) * 32 + j];
    }
    __syncthreads();

    for (int i = tid; i < 9 * 64; i += 320) {
        int kk = i >> 6, px = i & 63;
        int ky = kk / 3, kx = kk - ky * 3;
        float dy = osm[px * 33 + 2 * kk];
        float dx = osm[px * 33 + 2 * kk + 1];
        float m  = osm[px * 33 + 18 + kk];
        float py  = (float)(h - 1 + ky) + dy;
        float pxf = (float)(w0 + px - 1 + kx) + dx;
        float y0f = floorf(py), x0f = floorf(pxf);
        float wy = py - y0f, wx = pxf - x0f;
        int y0 = (int)y0f, x0 = (int)x0f;
        int y1 = y0 + 1, x1 = x0 + 1;
        float w00 = (1.f - wy) * (1.f - wx) * m;
        float w01 = (1.f - wy) * wx * m;
        float w10 = wy * (1.f - wx) * m;
        float w11 = wy * wx * m;
        if ((unsigned)y0 >= 128u) { w00 = 0.f; w01 = 0.f; }
        if ((unsigned)y1 >= 128u) { w10 = 0.f; w11 = 0.f; }
        if ((unsigned)x0 >= 128u) { w00 = 0.f; w10 = 0.f; }
        if ((unsigned)x1 >= 128u) { w01 = 0.f; w11 = 0.f; }
        int yc0 = min(max(y0, 0), 127), yc1 = min(max(y1, 0), 127);
        int xc0 = min(max(x0, 0), 127), xc1 = min(max(x1, 0), 127);
        ibuf[i] = make_int4((yc0 * 128 + xc0) * 64, (yc0 * 128 + xc1) * 64,
                            (yc1 * 128 + xc0) * 64, (yc1 * 128 + xc1) * 64);
        wbuf[i] = make_float4(w00, w01, w10, w11);
    }
    __syncthreads();

    const float* bbase = g_x2 + (size_t)b * NPIX * 64;
    int pxs = lane >> 3;
    int c8  = lane & 7;

    auto prefetch = [&](const int4* ib, const float4* wb, int it,
                        float4* r, float4& wtv, uint32_t& by) {
        int half = it & 1;
        int px = (it >> 1) * 4 + pxs;
        int4 off = ib[px];
        wtv = wb[px];
        int c4 = half * 8 + c8;
        r[0] = ((const float4*)(bbase + off.x))[c4];
        r[1] = ((const float4*)(bbase + off.y))[c4];
        r[2] = ((const float4*)(bbase + off.z))[c4];
        r[3] = ((const float4*)(bbase + off.w))[c4];
        by = (uint32_t)(px * S_STRIDE + c4 * 8);
    };
    auto cvst = [&](const float4* r, float4 wtv, uint32_t by, char* dh, char* dl) {
        float v0 = wtv.x * r[0].x + wtv.y * r[1].x + wtv.z * r[2].x + wtv.w * r[3].x;
        float v1 = wtv.x * r[0].y + wtv.y * r[1].y + wtv.z * r[2].y + wtv.w * r[3].y;
        float v2 = wtv.x * r[0].z + wtv.y * r[1].z + wtv.z * r[2].z + wtv.w * r[3].z;
        float v3 = wtv.x * r[0].w + wtv.y * r[1].w + wtv.z * r[2].w + wtv.w * r[3].w;
        float h0 = bf16_hi(v0), h1 = bf16_hi(v1);
        float h2 = bf16_hi(v2), h3 = bf16_hi(v3);
        *(uint2*)(dh + by) = make_uint2(pack_bf16x2(h0, h1), pack_bf16x2(h2, h3));
        *(uint2*)(dl + by) = make_uint2(pack_bf16x2(v0 - h0, v1 - h1),
                                        pack_bf16x2(v2 - h2, v3 - h3));
    };

    if (warp < 2) {
        // ---------------- producers ----------------
        int pw = warp;
        for (int kk = 0; kk < 9; kk++) {
            int p = kk & 1;
            if (kk >= 2) bar_sync_n(3 + p);   // wait buffer freed
            char* nh = smp + p * 9216;
            char* nl = smp + 18432 + p * 9216;
            const int4* ib = ibuf + kk * 64;
            const float4* wb = wbuf + kk * 64;

            float4 ra[2][4]; float4 rw_[2]; uint32_t rby[2];
            prefetch(ib, wb, pw,     ra[0], rw_[0], rby[0]);
            prefetch(ib, wb, pw + 2, ra[1], rw_[1], rby[1]);
#pragma unroll 4
            for (int i = 0; i < 16; i++) {
                int cur = i & 1;
                float4 sv0 = ra[cur][0], sv1 = ra[cur][1];
                float4 sv2 = ra[cur][2], sv3 = ra[cur][3];
                float4 sw = rw_[cur]; uint32_t sby = rby[cur];
                if (i + 2 < 16)
                    prefetch(ib, wb, pw + 2 * (i + 2), ra[cur], rw_[cur], rby[cur]);
                float4 sv[4] = {sv0, sv1, sv2, sv3};
                cvst(sv, sw, sby, nh, nl);
            }
            asm volatile("membar.cta;" ::: "memory");
            bar_arrive_n(1 + p);              // signal buffer full
        }
    } else {
        // ---------------- consumers ----------------
        int cw = warp - 2;
        int warp_m = cw >> 1;    // 0..3
        int warp_n = cw & 1;     // 0..1

        float acc[2][4][4];
#pragma unroll
        for (int mt = 0; mt < 2; mt++)
#pragma unroll
            for (int nt = 0; nt < 4; nt++)
#pragma unroll
                for (int j = 0; j < 4; j++) acc[mt][nt][j] = 0.f;

        for (int kk = 0; kk < 9; kk++) {
            int p = kk & 1;
            bar_sync_n(1 + p);                // wait buffer full
            char* sh = smp + p * 9216;
            char* sl = smp + 18432 + p * 9216;
            const uint4* wf_hi = g_wfhi + (kk * 8) * 4 * 32;
            const uint4* wf_lo = g_wflo + (kk * 8) * 4 * 32;
#pragma unroll
            for (int ks = 0; ks < 4; ks++) {
                uint4 ah0 = __ldg(&wf_hi[((warp_m * 2 + 0) * 4 + ks) * 32 + lane]);
                uint4 ah1 = __ldg(&wf_hi[((warp_m * 2 + 1) * 4 + ks) * 32 + lane]);
                uint32_t bh0[4], bh1[4], bl0[4], bl1[4];
#pragma unroll
                for (int nt = 0; nt < 4; nt++) {
                    int npx = warp_n * 32 + nt * 8 + g;
                    uint32_t base = (uint32_t)(npx * S_STRIDE + ks * 32 + t * 4);
                    bh0[nt] = *(const uint32_t*)(sh + base);
                    bh1[nt] = *(const uint32_t*)(sh + base + 16);
                    bl0[nt] = *(const uint32_t*)(sl + base);
                    bl1[nt] = *(const uint32_t*)(sl + base + 16);
                }
#pragma unroll
                for (int nt = 0; nt < 4; nt++) {
                    mma_bf16(acc[0][nt], (const uint32_t*)&ah0, bh0[nt], bh1[nt]);
                    mma_bf16(acc[1][nt], (const uint32_t*)&ah1, bh0[nt], bh1[nt]);
                    mma_bf16(acc[0][nt], (const uint32_t*)&ah0, bl0[nt], bl1[nt]);
                    mma_bf16(acc[1][nt], (const uint32_t*)&ah1, bl0[nt], bl1[nt]);
                }
                uint4 al0 = __ldg(&wf_lo[((warp_m * 2 + 0) * 4 + ks) * 32 + lane]);
                uint4 al1 = __ldg(&wf_lo[((warp_m * 2 + 1) * 4 + ks) * 32 + lane]);
#pragma unroll
                for (int nt = 0; nt < 4; nt++) {
                    mma_bf16(acc[0][nt], (const uint32_t*)&al0, bh0[nt], bh1[nt]);
                    mma_bf16(acc[1][nt], (const uint32_t*)&al1, bh0[nt], bh1[nt]);
                }
            }
            bar_arrive_n(3 + p);              // signal buffer free
        }

        // epilogue: direct STG from C fragments
        float* ob = out + ((size_t)b * COUT) * NPIX + h * WW + w0;
#pragma unroll
        for (int mt = 0; mt < 2; mt++) {
            int o = warp_m * 32 + mt * 16 + g;
#pragma unroll
            for (int nt = 0; nt < 4; nt++) {
                int px = warp_n * 32 + nt * 8 + 2 * t;
                float* p0 = ob + (size_t)o * NPIX + px;
                *(float2*)p0 = make_float2(acc[mt][nt][0], acc[mt][nt][1]);
                float* p1 = p0 + 8 * (size_t)NPIX;
                *(float2*)p1 = make_float2(acc[mt][nt][2], acc[mt][nt][3]);
            }
        }
    }
}

// ---------------------------------------------------------------------------
extern "C" void kernel_launch(void* const* d_in, const int* in_sizes, int n_in,
                              void* d_out, int out_size) {
    const float* x     = (const float*)d_in[0];
    const float* pre_w = (const float*)d_in[1];
    const float* pre_b = (const float*)d_in[2];
    const float* off_w = (const float*)d_in[3];
    const float* off_b = (const float*)d_in[4];
    const float* mod_w = (const float*)d_in[5];
    const float* mod_b = (const float*)d_in[6];
    const float* reg_w = (const float*)d_in[7];
    float* out = (float*)d_out;

    cudaFuncSetAttribute(k2_offmask, cudaFuncAttributeMaxDynamicSharedMemorySize, K2_SMEM_BYTES);
    cudaFuncSetAttribute(k3_main, cudaFuncAttributeMaxDynamicSharedMemorySize, K3_SMEM_BYTES);

    k0_wt<<<36, 256>>>(reg_w, off_w, mod_w);
    k1_pre<<<BB * HH, 128>>>(x, pre_w, pre_b);
    k2_offmask<<<BB * HH, 256, K2_SMEM_BYTES>>>(off_b, mod_b);
    k3_main<<<BB * HH * 2, 320, K3_SMEM_BYTES>>>(out);
}

// round 9
// speedup vs baseline: 1.0890x; 1.0890x over previous
#include <cuda_runtime.h>
#include <cuda_bf16.h>
#include <math.h>
#include <stdint.h>

#define BB    8
#define CIN   64
#define HH    128
#define WW    128
#define COUT  128
#define NPIX  (HH*WW)           // 16384
#define KTOT  (9*CIN)           // 576

// Scratch (__device__ globals; no allocation)
__device__ float g_x2 [BB*NPIX*CIN];          // NHWC fp32: [b][h][w][c]
__device__ __nv_bfloat16 g_xbhi[BB*NPIX*CIN]; // NHWC bf16 hi
__device__ __nv_bfloat16 g_xblo[BB*NPIX*CIN]; // NHWC bf16 lo
__device__ float g_offm[BB*NPIX*32];          // per-pixel [32]: 0..17 off, 18..26 mask
__device__ uint4 g_wfhi[9*8*4*32];            // k3 A frags (hi): [kk][mtile8][ks4][lane32]
__device__ uint4 g_wflo[9*8*4*32];            // k3 A frags (lo)
__device__ uint4 g_w2fhi[9*2*4*32];           // k2 A frags (hi): [kk][mtile2][ks4][lane32]
__device__ uint4 g_w2flo[9*2*4*32];           // k2 A frags (lo)

__device__ __forceinline__ uint32_t pack_bf16x2(float e0, float e1) {
    uint32_t r;
    asm("cvt.rn.bf16x2.f32 %0, %1, %2;" : "=r"(r) : "f"(e1), "f"(e0));
    return r;
}
__device__ __forceinline__ float bf16_hi(float v) {
    __nv_bfloat16 hb = __float2bfloat16(v);
    return __bfloat162float(hb);
}
__device__ __forceinline__ void mma_bf16(float* d, const uint32_t* a, uint32_t b0, uint32_t b1) {
    asm volatile(
        "mma.sync.aligned.m16n8k16.row.col.f32.bf16.bf16.f32 "
        "{%0,%1,%2,%3}, {%4,%5,%6,%7}, {%8,%9}, {%0,%1,%2,%3};"
        : "+f"(d[0]), "+f"(d[1]), "+f"(d[2]), "+f"(d[3])
        : "r"(a[0]), "r"(a[1]), "r"(a[2]), "r"(a[3]), "r"(b0), "r"(b1));
}
__device__ __forceinline__ uint32_t smem_u32(const void* p) {
    uint32_t a;
    asm("{ .reg .u64 t; cvta.to.shared.u64 t, %1; cvt.u32.u64 %0, t; }" : "=r"(a) : "l"(p));
    return a;
}
__device__ __forceinline__ void ldsm_x4(uint32_t& r0, uint32_t& r1, uint32_t& r2, uint32_t& r3,
                                        uint32_t addr) {
    asm volatile("ldmatrix.sync.aligned.m8n8.x4.shared.b16 {%0,%1,%2,%3}, [%4];"
                 : "=r"(r0), "=r"(r1), "=r"(r2), "=r"(r3) : "r"(addr));
}

// ---------------------------------------------------------------------------
// K0: weight prep — pre-packed mma A fragments (hi/lo) for k3 and k2.
// ---------------------------------------------------------------------------
__global__ void k0_wt(const float* __restrict__ rw,
                      const float* __restrict__ off_w,
                      const float* __restrict__ mod_w) {
    int i = blockIdx.x * 256 + threadIdx.x;
    if (i < 9 * 8 * 4 * 32) {
        int kk   = i >> 10;
        int rem  = i & 1023;
        int mt   = rem >> 7;
        int rem2 = rem & 127;
        int ks   = rem2 >> 5;
        int lane = rem2 & 31;
        int g = lane >> 2, t = lane & 3;
        int o0 = mt * 16 + g, o1 = o0 + 8;
        int c0 = ks * 16 + 2 * t, c1 = c0 + 8;

        float w00a = rw[(o0 * 64 + c0) * 9 + kk];
        float w00b = rw[(o0 * 64 + c0 + 1) * 9 + kk];
        float w10a = rw[(o1 * 64 + c0) * 9 + kk];
        float w10b = rw[(o1 * 64 + c0 + 1) * 9 + kk];
        float w01a = rw[(o0 * 64 + c1) * 9 + kk];
        float w01b = rw[(o0 * 64 + c1 + 1) * 9 + kk];
        float w11a = rw[(o1 * 64 + c1) * 9 + kk];
        float w11b = rw[(o1 * 64 + c1 + 1) * 9 + kk];

        float h00a = bf16_hi(w00a), h00b = bf16_hi(w00b);
        float h10a = bf16_hi(w10a), h10b = bf16_hi(w10b);
        float h01a = bf16_hi(w01a), h01b = bf16_hi(w01b);
        float h11a = bf16_hi(w11a), h11b = bf16_hi(w11b);

        uint4 hi, lo;
        hi.x = pack_bf16x2(h00a, h00b);
        hi.y = pack_bf16x2(h10a, h10b);
        hi.z = pack_bf16x2(h01a, h01b);
        hi.w = pack_bf16x2(h11a, h11b);
        lo.x = pack_bf16x2(w00a - h00a, w00b - h00b);
        lo.y = pack_bf16x2(w10a - h10a, w10b - h10b);
        lo.z = pack_bf16x2(w01a - h01a, w01b - h01b);
        lo.w = pack_bf16x2(w11a - h11a, w11b - h11b);
        g_wfhi[i] = hi;
        g_wflo[i] = lo;
    }
    if (i < 9 * 2 * 4 * 32) {
        int lane = i & 31;
        int ks = (i >> 5) & 3;
        int mt = (i >> 7) & 1;
        int kk = i >> 8;
        int g = lane >> 2, t = lane & 3;
        int o0 = mt * 16 + g, o1 = o0 + 8;
        int c0 = ks * 16 + 2 * t, c1 = c0 + 8;

        auto w2v = [&](int o, int c) -> float {
            if (o < 18)      return off_w[(o * 64 + c) * 9 + kk];
            else if (o < 27) return mod_w[((o - 18) * 64 + c) * 9 + kk];
            return 0.f;
        };
        float w00a = w2v(o0, c0), w00b = w2v(o0, c0 + 1);
        float w10a = w2v(o1, c0), w10b = w2v(o1, c0 + 1);
        float w01a = w2v(o0, c1), w01b = w2v(o0, c1 + 1);
        float w11a = w2v(o1, c1), w11b = w2v(o1, c1 + 1);

        float h00a = bf16_hi(w00a), h00b = bf16_hi(w00b);
        float h10a = bf16_hi(w10a), h10b = bf16_hi(w10b);
        float h01a = bf16_hi(w01a), h01b = bf16_hi(w01b);
        float h11a = bf16_hi(w11a), h11b = bf16_hi(w11b);

        uint4 hi, lo;
        hi.x = pack_bf16x2(h00a, h00b);
        hi.y = pack_bf16x2(h10a, h10b);
        hi.z = pack_bf16x2(h01a, h01b);
        hi.w = pack_bf16x2(h11a, h11b);
        lo.x = pack_bf16x2(w00a - h00a, w00b - h00b);
        lo.y = pack_bf16x2(w10a - h10a, w10b - h10b);
        lo.z = pack_bf16x2(w01a - h01a, w01b - h01b);
        lo.w = pack_bf16x2(w11a - h11a, w11b - h11b);
        g_w2fhi[i] = hi;
        g_w2flo[i] = lo;
    }
}

// ---------------------------------------------------------------------------
// K1: 1x1 pre-conv, NCHW in -> NHWC fp32 (g_x2) + NHWC bf16 hi/lo
// ---------------------------------------------------------------------------
__global__ void __launch_bounds__(128) k1_pre(const float* __restrict__ x,
                                              const float* __restrict__ pre_w,
                                              const float* __restrict__ pre_b) {
    __shared__ float wsm[64 * 64];
    __shared__ float bsm[64];
    int tid = threadIdx.x;
    for (int i = tid; i < 4096; i += 128) {
        int co = i & 63, ci = i >> 6;
        wsm[ci * 64 + co] = pre_w[co * 64 + ci];
    }
    if (tid < 64) bsm[tid] = pre_b[tid];
    __syncthreads();

    int bh = blockIdx.x;
    int b = bh >> 7, h = bh & 127;
    int w = tid;

    const float* xp = x + (size_t)b * 64 * NPIX + h * WW + w;
    float xin[64];
#pragma unroll
    for (int ci = 0; ci < 64; ci++) xin[ci] = xp[(size_t)ci * NPIX];

    size_t pbase = ((size_t)bh * WW + w) * 64;
    float4* out4 = (float4*)(g_x2 + pbase);
    const float4* wsm4 = (const float4*)wsm;
    const float4* b4 = (const float4*)bsm;
#pragma unroll
    for (int cog = 0; cog < 16; cog++) {
        float4 acc = b4[cog];
#pragma unroll
        for (int ci = 0; ci < 64; ci++) {
            float4 wv = wsm4[ci * 16 + cog];
            acc.x += xin[ci] * wv.x;
            acc.y += xin[ci] * wv.y;
            acc.z += xin[ci] * wv.z;
            acc.w += xin[ci] * wv.w;
        }
        out4[cog] = acc;
        float h0 = bf16_hi(acc.x), h1 = bf16_hi(acc.y);
        float h2 = bf16_hi(acc.z), h3 = bf16_hi(acc.w);
        uint2 vh = make_uint2(pack_bf16x2(h0, h1), pack_bf16x2(h2, h3));
        uint2 vl = make_uint2(pack_bf16x2(acc.x - h0, acc.y - h1),
                              pack_bf16x2(acc.z - h2, acc.w - h3));
        *(uint2*)(g_xbhi + pbase + cog * 4) = vh;
        *(uint2*)(g_xblo + pbase + cog * 4) = vl;
    }
}

// ---------------------------------------------------------------------------
// K2: offset+mask 3x3 conv via HMMA hi/lo 3-pass + ldmatrix B-frags.
// ---------------------------------------------------------------------------
extern __shared__ float dyn_smem[];
#define S_STRIDE  144   // bytes per px row (72 bf16)

__global__ void __launch_bounds__(256) k2_offmask(const float* __restrict__ off_b,
                                                  const float* __restrict__ mod_b) {
    char* smp = (char*)dyn_smem;
    char* s_hi = smp;
    char* s_lo = smp + 18432;

    int tid = threadIdx.x;
    int warp = tid >> 5, lane = tid & 31;
    int g = lane >> 2, t = lane & 3;
    int bx = blockIdx.x;
    int b = bx >> 7, h = bx & 127;
    size_t pixbase = (size_t)bx * 128;

    int warp_m = warp >> 2;     // 0..1
    int warp_n = warp & 3;      // 0..3

    // ldmatrix addressing: pair selects matrix, rr = row within 8x8
    int pair = lane >> 3, rr = lane & 7;
    uint32_t su32 = smem_u32(smp);
    uint32_t rowpart = (uint32_t)((warp_n * 32 + ((pair >> 1) << 3) + rr) * S_STRIDE
                                  + (pair & 1) * 16);

    float acc[4][4];
#pragma unroll
    for (int nt = 0; nt < 4; nt++)
#pragma unroll
        for (int j = 0; j < 4; j++) acc[nt][j] = 0.f;

    for (int kk = 0; kk < 9; kk++) {
        int ky = kk / 3, kx = kk - ky * 3;
        __syncthreads();
        int y = h - 1 + ky;
        bool yok = (unsigned)y < 128u;
        const __nv_bfloat16* rh = g_xbhi + ((size_t)(b * 128 + (yok ? y : 0)) * 128) * 64;
        const __nv_bfloat16* rl = g_xblo + ((size_t)(b * 128 + (yok ? y : 0)) * 128) * 64;
        for (int i = tid; i < 2048; i += 256) {
            int px = i >> 4, c4 = i & 15;
            int xg = px - 1 + kx;
            uint2 vh = make_uint2(0u, 0u), vl = make_uint2(0u, 0u);
            if (yok && (unsigned)xg < 128u) {
                vh = *(const uint2*)(rh + xg * 64 + c4 * 4);
                vl = *(const uint2*)(rl + xg * 64 + c4 * 4);
            }
            *(uint2*)(s_hi + px * S_STRIDE + c4 * 8) = vh;
            *(uint2*)(s_lo + px * S_STRIDE + c4 * 8) = vl;
        }
        __syncthreads();

        const uint4* wfh = g_w2fhi + (kk * 2 + warp_m) * 4 * 32;
        const uint4* wfl = g_w2flo + (kk * 2 + warp_m) * 4 * 32;
#pragma unroll
        for (int ks = 0; ks < 4; ks++) {
            uint4 ah = __ldg(&wfh[ks * 32 + lane]);
            uint4 al = __ldg(&wfl[ks * 32 + lane]);
            uint32_t bh0[4], bh1[4], bl0[4], bl1[4];
            uint32_t hb = su32 + rowpart + ks * 32;
            ldsm_x4(bh0[0], bh1[0], bh0[1], bh1[1], hb);
            ldsm_x4(bh0[2], bh1[2], bh0[3], bh1[3], hb + 16 * S_STRIDE);
            ldsm_x4(bl0[0], bl1[0], bl0[1], bl1[1], hb + 18432);
            ldsm_x4(bl0[2], bl1[2], bl0[3], bl1[3], hb + 18432 + 16 * S_STRIDE);
#pragma unroll
            for (int nt = 0; nt < 4; nt++) {
                mma_bf16(acc[nt], (const uint32_t*)&ah, bh0[nt], bh1[nt]);
                mma_bf16(acc[nt], (const uint32_t*)&ah, bl0[nt], bl1[nt]);
                mma_bf16(acc[nt], (const uint32_t*)&al, bh0[nt], bh1[nt]);
            }
        }
    }

    int o0 = warp_m * 16 + g, o1 = o0 + 8;
    auto wr = [&](int o, int px, float v) {
        if (o >= 27) return;
        v += (o < 18) ? __ldg(off_b + o) : __ldg(mod_b + o - 18);
        if (o >= 18) v = 2.0f / (1.0f + expf(-v));
        g_offm[(pixbase + px) * 32 + o] = v;
    };
#pragma unroll
    for (int nt = 0; nt < 4; nt++) {
        int px = warp_n * 32 + nt * 8 + 2 * t;
        wr(o0, px,     acc[nt][0]);
        wr(o0, px + 1, acc[nt][1]);
        wr(o1, px,     acc[nt][2]);
        wr(o1, px + 1, acc[nt][3]);
    }
}
#define K2_SMEM_BYTES 36864

// ---------------------------------------------------------------------------
// K3: deformable sampling + HMMA hi/lo 3-pass, software-pipelined (R7) +
// ldmatrix B-frags. Block = half row (64 px), 256 threads / 8 warps, 2 CTAs/SM.
// smem: s_hi[2],s_lo[2] (4x9216=36864) | OSM 36864 | IBUF 45312 | WBUF 54528
// ---------------------------------------------------------------------------
#define OSM_OFF   36864
#define IBUF_OFF  45312
#define WBUF_OFF  54528
#define K3_SMEM_BYTES 63744

__global__ void __launch_bounds__(256, 2) k3_main(float* __restrict__ out) {
    char* smp = (char*)dyn_smem;

    int tid = threadIdx.x;
    int warp = tid >> 5, lane = tid & 31;
    int g = lane >> 2, t = lane & 3;
    int bx = blockIdx.x;
    int b = bx >> 8;
    int h = (bx >> 1) & 127;
    int seg = bx & 1;
    int w0 = seg * 64;
    size_t pixbase = (((size_t)(b * 128 + h)) * 128 + w0);

    float* osm = (float*)(smp + OSM_OFF);
    int4* ibuf = (int4*)(smp + IBUF_OFF);
    float4* wbuf = (float4*)(smp + WBUF_OFF);

    for (int i = tid; i < 2048; i += 256) {
        int px = i >> 5, j = i & 31;
        osm[px * 33 + j] = g_offm[(pixbase + px) * 32 + j];
    }
    __syncthreads();

    for (int i = tid; i < 9 * 64; i += 256) {
        int kk = i >> 6, px = i & 63;
        int ky = kk / 3, kx = kk - ky * 3;
        float dy = osm[px * 33 + 2 * kk];
        float dx = osm[px * 33 + 2 * kk + 1];
        float m  = osm[px * 33 + 18 + kk];
        float py  = (float)(h - 1 + ky) + dy;
        float pxf = (float)(w0 + px - 1 + kx) + dx;
        float y0f = floorf(py), x0f = floorf(pxf);
        float wy = py - y0f, wx = pxf - x0f;
        int y0 = (int)y0f, x0 = (int)x0f;
        int y1 = y0 + 1, x1 = x0 + 1;
        float w00 = (1.f - wy) * (1.f - wx) * m;
        float w01 = (1.f - wy) * wx * m;
        float w10 = wy * (1.f - wx) * m;
        float w11 = wy * wx * m;
        if ((unsigned)y0 >= 128u) { w00 = 0.f; w01 = 0.f; }
        if ((unsigned)y1 >= 128u) { w10 = 0.f; w11 = 0.f; }
        if ((unsigned)x0 >= 128u) { w00 = 0.f; w10 = 0.f; }
        if ((unsigned)x1 >= 128u) { w01 = 0.f; w11 = 0.f; }
        int yc0 = min(max(y0, 0), 127), yc1 = min(max(y1, 0), 127);
        int xc0 = min(max(x0, 0), 127), xc1 = min(max(x1, 0), 127);
        ibuf[i] = make_int4((yc0 * 128 + xc0) * 64, (yc0 * 128 + xc1) * 64,
                            (yc1 * 128 + xc0) * 64, (yc1 * 128 + xc1) * 64);
        wbuf[i] = make_float4(w00, w01, w10, w11);
    }
    __syncthreads();

    const float* bbase = g_x2 + (size_t)b * NPIX * 64;
    int pxs = lane >> 3;
    int c8  = lane & 7;

    int warp_m = warp >> 1;
    int warp_n = warp & 1;

    // ldmatrix addressing
    int pair = lane >> 3, rr = lane & 7;
    uint32_t su32 = smem_u32(smp);
    uint32_t rowpart = (uint32_t)((warp_n * 32 + ((pair >> 1) << 3) + rr) * S_STRIDE
                                  + (pair & 1) * 16);

    float acc[2][4][4];
#pragma unroll
    for (int mt = 0; mt < 2; mt++)
#pragma unroll
        for (int nt = 0; nt < 4; nt++)
#pragma unroll
            for (int j = 0; j < 4; j++) acc[mt][nt][j] = 0.f;

    auto prefetch = [&](const int4* ib, const float4* wb, int it,
                        float4* r, float4& wtv, uint32_t& by) {
        int half = it & 1;
        int px = (it >> 1) * 4 + pxs;
        int4 off = ib[px];
        wtv = wb[px];
        int c4 = half * 8 + c8;
        r[0] = ((const float4*)(bbase + off.x))[c4];
        r[1] = ((const float4*)(bbase + off.y))[c4];
        r[2] = ((const float4*)(bbase + off.z))[c4];
        r[3] = ((const float4*)(bbase + off.w))[c4];
        by = (uint32_t)(px * S_STRIDE + c4 * 8);
    };
    auto cvst = [&](const float4* r, float4 wtv, uint32_t by, char* dh, char* dl) {
        float v0 = wtv.x * r[0].x + wtv.y * r[1].x + wtv.z * r[2].x + wtv.w * r[3].x;
        float v1 = wtv.x * r[0].y + wtv.y * r[1].y + wtv.z * r[2].y + wtv.w * r[3].y;
        float v2 = wtv.x * r[0].z + wtv.y * r[1].z + wtv.z * r[2].z + wtv.w * r[3].z;
        float v3 = wtv.x * r[0].w + wtv.y * r[1].w + wtv.z * r[2].w + wtv.w * r[3].w;
        float h0 = bf16_hi(v0), h1 = bf16_hi(v1);
        float h2 = bf16_hi(v2), h3 = bf16_hi(v3);
        *(uint2*)(dh + by) = make_uint2(pack_bf16x2(h0, h1), pack_bf16x2(h2, h3));
        *(uint2*)(dl + by) = make_uint2(pack_bf16x2(v0 - h0, v1 - h1),
                                        pack_bf16x2(v2 - h2, v3 - h3));
    };

    // prologue: fill s[0] with kk=0 samples
    {
        float4 r[4]; float4 wtv; uint32_t by;
        for (int it = warp; it < 32; it += 8) {
            prefetch(ibuf, wbuf, it, r, wtv, by);
            cvst(r, wtv, by, smp, smp + 18432);
        }
    }
    __syncthreads();

    for (int kk = 0; kk < 9; kk++) {
        int p = kk & 1;
        char* nh = smp + (p ^ 1) * 9216;
        char* nl = smp + 18432 + (p ^ 1) * 9216;
        const uint4* wf_hi = g_wfhi + (kk * 8) * 4 * 32;
        const uint4* wf_lo = g_wflo + (kk * 8) * 4 * 32;
        const int4* ib1 = ibuf + (kk + 1) * 64;
        const float4* wb1 = wbuf + (kk + 1) * 64;
        bool pf = (kk < 8);
        uint32_t sbh = su32 + p * 9216 + rowpart;

        float4 ra[2][4]; float4 rw_[2]; uint32_t rby[2];
        if (pf) {
            prefetch(ib1, wb1, warp,     ra[0], rw_[0], rby[0]);
            prefetch(ib1, wb1, warp + 8, ra[1], rw_[1], rby[1]);
        }

        auto do_mma2 = [&](int ks0) {
#pragma unroll
            for (int ks = ks0; ks < ks0 + 2; ks++) {
                uint4 ah0 = __ldg(&wf_hi[((warp_m * 2 + 0) * 4 + ks) * 32 + lane]);
                uint4 ah1 = __ldg(&wf_hi[((warp_m * 2 + 1) * 4 + ks) * 32 + lane]);
                uint32_t bh0[4], bh1[4], bl0[4], bl1[4];
                uint32_t hb = sbh + ks * 32;
                ldsm_x4(bh0[0], bh1[0], bh0[1], bh1[1], hb);
                ldsm_x4(bh0[2], bh1[2], bh0[3], bh1[3], hb + 16 * S_STRIDE);
                ldsm_x4(bl0[0], bl1[0], bl0[1], bl1[1], hb + 18432);
                ldsm_x4(bl0[2], bl1[2], bl0[3], bl1[3], hb + 18432 + 16 * S_STRIDE);
#pragma unroll
                for (int nt = 0; nt < 4; nt++) {
                    mma_bf16(acc[0][nt], (const uint32_t*)&ah0, bh0[nt], bh1[nt]);
                    mma_bf16(acc[1][nt], (const uint32_t*)&ah1, bh0[nt], bh1[nt]);
                    mma_bf16(acc[0][nt], (const uint32_t*)&ah0, bl0[nt], bl1[nt]);
                    mma_bf16(acc[1][nt], (const uint32_t*)&ah1, bl0[nt], bl1[nt]);
                }
                uint4 al0 = __ldg(&wf_lo[((warp_m * 2 + 0) * 4 + ks) * 32 + lane]);
                uint4 al1 = __ldg(&wf_lo[((warp_m * 2 + 1) * 4 + ks) * 32 + lane]);
#pragma unroll
                for (int nt = 0; nt < 4; nt++) {
                    mma_bf16(acc[0][nt], (const uint32_t*)&al0, bh0[nt], bh1[nt]);
                    mma_bf16(acc[1][nt], (const uint32_t*)&al1, bh0[nt], bh1[nt]);
                }
            }
        };

        do_mma2(0);

        if (pf) {
            cvst(ra[0], rw_[0], rby[0], nh, nl);
            cvst(ra[1], rw_[1], rby[1], nh, nl);
            prefetch(ib1, wb1, warp + 16, ra[0], rw_[0], rby[0]);
            prefetch(ib1, wb1, warp + 24, ra[1], rw_[1], rby[1]);
        }

        do_mma2(2);

        if (pf) {
            cvst(ra[0], rw_[0], rby[0], nh, nl);
            cvst(ra[1], rw_[1], rby[1], nh, nl);
        }
        __syncthreads();
    }

    // epilogue: direct STG from C fragments
    float* ob = out + ((size_t)b * COUT) * NPIX + h * WW + w0;
#pragma unroll
    for (int mt = 0; mt < 2; mt++) {
        int o = warp_m * 32 + mt * 16 + g;
#pragma unroll
        for (int nt = 0; nt < 4; nt++) {
            int px = warp_n * 32 + nt * 8 + 2 * t;
            float* p0 = ob + (size_t)o * NPIX + px;
            *(float2*)p0 = make_float2(acc[mt][nt][0], acc[mt][nt][1]);
            float* p1 = p0 + 8 * (size_t)NPIX;
            *(float2*)p1 = make_float2(acc[mt][nt][2], acc[mt][nt][3]);
        }
    }
}

// ---------------------------------------------------------------------------
extern "C" void kernel_launch(void* const* d_in, const int* in_sizes, int n_in,
                              void* d_out, int out_size) {
    const float* x     = (const float*)d_in[0];
    const float* pre_w = (const float*)d_in[1];
    const float* pre_b = (const float*)d_in[2];
    const float* off_w = (const float*)d_in[3];
    const float* off_b = (const float*)d_in[4];
    const float* mod_w = (const float*)d_in[5];
    const float* mod_b = (const float*)d_in[6];
    const float* reg_w = (const float*)d_in[7];
    float* out = (float*)d_out;

    cudaFuncSetAttribute(k2_offmask, cudaFuncAttributeMaxDynamicSharedMemorySize, K2_SMEM_BYTES);
    cudaFuncSetAttribute(k3_main, cudaFuncAttributeMaxDynamicSharedMemorySize, K3_SMEM_BYTES);

    k0_wt<<<36, 256>>>(reg_w, off_w, mod_w);
    k1_pre<<<BB * HH, 128>>>(x, pre_w, pre_b);
    k2_offmask<<<BB * HH, 256, K2_SMEM_BYTES>>>(off_b, mod_b);
    k3_main<<<BB * HH * 2, 256, K3_SMEM_BYTES>>>(out);
}